// round 13
// baseline (speedup 1.0000x reference)
#include <cuda_runtime.h>
#include <cuda_bf16.h>
#include <math_constants.h>
#include <cstdint>

#define BB 32
#define CC 9
#define TT 4096
#define NC 512
#define CD 64
#define MBLK 128          // positions per block
#define KP_B 272          // padded SMEM row stride bytes (128B hi + 128B lo + 16 pad)
#define CROWS 64          // codes per chunk (8 chunks)
#define NROWS (BB * CC)   // 288 real rows
#define NPAIR (NROWS / 2) // 144 packed FFTs

#define OFF_IDX ((size_t)BB * TT * CD)
#define OFF_PH  (OFF_IDX + (size_t)BB * TT)

// SMEM map for quant kernel (bytes)
#define SM_A    0u        // 128 * 272 = 34816
#define SM_B0   34816u    // 3 buffers x 64 * 272 = 17408 each
#define SM_CN   87040u    // 2048
#define SM_RBV  89088u    // float [128][2]
#define SM_RBI  90112u    // int   [128][2]
#define SM_IDX  91136u    // int   [128]
#define SMEMSZ  91648     // 2 CTAs/SM

// FFT smem: tw float2[4096] | sr float[4224] | si float[4224]
#define FFT_SMEM (2 * TT * 4 + 2 * (TT + TT / 32) * 4)   // 66560
#define PIDX(i) ((i) + ((i) >> 5))

// ---------------- global scratch ----------------
__device__ float g_phase[BB * CC * TT];
__device__ __align__(16) __nv_bfloat16 g_B[NC * 128];    // per code: hi[64] | lo[64]
__device__ float g_cn[NC];

__device__ __forceinline__ uint32_t smem_to_u32(const void* p) {
    uint32_t a;
    asm("{ .reg .u64 t; cvta.to.shared.u64 t, %1; cvt.u32.u64 %0, t; }"
        : "=r"(a) : "l"(p));
    return a;
}

#define LDSM_X4(r0, r1, r2, r3, addr) \
    asm volatile("ldmatrix.sync.aligned.m8n8.x4.shared.b16 {%0,%1,%2,%3}, [%4];" \
                 : "=r"(r0), "=r"(r1), "=r"(r2), "=r"(r3) : "r"(addr))

#define MMA16816(d, a, b0, b1) \
    asm volatile("mma.sync.aligned.m16n8k16.row.col.f32.bf16.bf16.f32 " \
                 "{%0,%1,%2,%3}, {%4,%5,%6,%7}, {%8,%9}, {%0,%1,%2,%3};" \
                 : "+f"((d)[0]), "+f"((d)[1]), "+f"((d)[2]), "+f"((d)[3]) \
                 : "r"((a)[0]), "r"((a)[1]), "r"((a)[2]), "r"((a)[3]), \
                   "r"(b0), "r"(b1))

#define CP_ASYNC16(saddr, gptr) \
    asm volatile("cp.async.cg.shared.global [%0], [%1], 16;" \
                 :: "r"(saddr), "l"(gptr) : "memory")
#define CP_COMMIT() asm volatile("cp.async.commit_group;" ::: "memory")
#define CP_WAIT(n)  asm volatile("cp.async.wait_group %0;" :: "n"(n) : "memory")

__device__ __forceinline__ float2 cmulf(float2 a, float2 b) {
    return make_float2(a.x * b.x - a.y * b.y, a.x * b.y + a.y * b.x);
}
__device__ __forceinline__ float2 f2add(float2 a, float2 b) {
    return make_float2(a.x + b.x, a.y + b.y);
}
__device__ __forceinline__ float2 f2sub(float2 a, float2 b) {
    return make_float2(a.x - b.x, a.y - b.y);
}

__device__ __forceinline__ void split_pack(float v0, float v1,
                                           uint32_t& hp, uint32_t& lp) {
    __nv_bfloat16 h0 = __float2bfloat16(v0), h1 = __float2bfloat16(v1);
    __nv_bfloat16 l0 = __float2bfloat16(v0 - __bfloat162float(h0));
    __nv_bfloat16 l1 = __float2bfloat16(v1 - __bfloat162float(h1));
    hp = ((uint32_t)__bfloat16_as_ushort(h1) << 16) | __bfloat16_as_ushort(h0);
    lp = ((uint32_t)__bfloat16_as_ushort(l1) << 16) | __bfloat16_as_ushort(l0);
}

// ---------------- kernel 1: packed Hilbert FFT + fused codebook convert ----
// Separate re/im planes with +1/32 padding: conflict-free butterflies.
__global__ void fft_conv_kernel(const float* __restrict__ imu,
                                const float* __restrict__ cb) {
    const int tid = threadIdx.x;

    if (blockIdx.x >= NPAIR) {
        // ---- codebook convert: warp per code (16 warps) ----
        const int wid = tid >> 5, lane = tid & 31;
        const int c = (blockIdx.x - NPAIR) * 16 + wid;
        const float2 v = ((const float2*)(cb + (size_t)c * CD))[lane];
        float n = v.x * v.x + v.y * v.y;
        uint32_t hp, lp;
        split_pack(v.x, v.y, hp, lp);
        uint32_t* row32 = (uint32_t*)(g_B + (size_t)c * 128);
        row32[lane] = hp;
        row32[32 + lane] = lp;
#pragma unroll
        for (int off = 16; off >= 1; off >>= 1)
            n += __shfl_xor_sync(0xffffffffu, n, off);
        if (lane == 0) g_cn[c] = n;
        return;
    }

    extern __shared__ float fsh[];
    float2* tw = (float2*)fsh;              // [4096]
    float* sr = fsh + 2 * TT;               // [4224] padded
    float* si = sr + (TT + TT / 32);        // [4224] padded
    const float* x0 = imu + (size_t)(2 * blockIdx.x) * TT;
    const float* x1 = x0 + TT;

    for (int k = tid; k < TT; k += 512) {
        float sn, cs;
        sincosf(-(float)CUDART_PI_F * (float)k / 2048.0f, &sn, &cs);
        tw[k] = make_float2(cs, sn);
    }
    for (int t = tid; t < TT; t += 512) {
        sr[PIDX(t)] = x0[t];
        si[PIDX(t)] = x1[t];
    }
    __syncthreads();

    // Forward radix-4 DIF: natural in, base-4 digit-reversed out.
#pragma unroll
    for (int ls = 10; ls >= 0; ls -= 2) {
        const int L = 1 << ls;
        const int m = 1024 >> ls;
        for (int i = tid; i < 1024; i += 512) {
            const int j = i & (L - 1);
            const int i0 = ((i >> ls) << (ls + 2)) + j;
            const int ia = PIDX(i0), ib = PIDX(i0 + L);
            const int ic = PIDX(i0 + 2 * L), id = PIDX(i0 + 3 * L);
            float2 a = make_float2(sr[ia], si[ia]);
            float2 b = make_float2(sr[ib], si[ib]);
            float2 c = make_float2(sr[ic], si[ic]);
            float2 d = make_float2(sr[id], si[id]);
            float2 t0 = f2add(a, c), t1 = f2sub(a, c);
            float2 t2 = f2add(b, d), t3 = f2sub(b, d);
            float2 r0 = f2add(t0, t2);
            float2 r1 = cmulf(make_float2(t1.x + t3.y, t1.y - t3.x), tw[j * m]);
            float2 r2 = cmulf(f2sub(t0, t2), tw[2 * j * m]);
            float2 r3 = cmulf(make_float2(t1.x - t3.y, t1.y + t3.x), tw[3 * j * m]);
            sr[ia] = r0.x; si[ia] = r0.y;
            sr[ib] = r1.x; si[ib] = r1.y;
            sr[ic] = r2.x; si[ic] = r2.y;
            sr[id] = r3.x; si[id] = r3.y;
        }
        __syncthreads();
    }

    // Hilbert multiplier M[k] = -i*sgn(k) at base-4 digit-reversed slot.
    for (int p = tid; p < TT; p += 512) {
        const int r = (int)(__brev((unsigned)p) >> 20);
        const int k = ((r & 0x555) << 1) | ((r >> 1) & 0x555);
        const int ip = PIDX(p);
        const float vx = sr[ip], vy = si[ip];
        if (k == 0 || k == TT / 2) { sr[ip] = 0.0f;  si[ip] = 0.0f; }
        else if (k < TT / 2)       { sr[ip] = vy;    si[ip] = -vx; }
        else                       { sr[ip] = -vy;   si[ip] = vx;  }
    }
    __syncthreads();

    // Inverse radix-4 DIT: digit-reversed in, natural out (conj twiddles, no 1/N).
#pragma unroll
    for (int ls = 0; ls <= 10; ls += 2) {
        const int L = 1 << ls;
        const int m = 1024 >> ls;
        for (int i = tid; i < 1024; i += 512) {
            const int j = i & (L - 1);
            const int i0 = ((i >> ls) << (ls + 2)) + j;
            const int ia = PIDX(i0), ib = PIDX(i0 + L);
            const int ic = PIDX(i0 + 2 * L), id = PIDX(i0 + 3 * L);
            float2 w1 = tw[j * m], w2 = tw[2 * j * m], w3 = tw[3 * j * m];
            float2 A = make_float2(sr[ia], si[ia]);
            float2 Bv = cmulf(make_float2(sr[ib], si[ib]), make_float2(w1.x, -w1.y));
            float2 Cv = cmulf(make_float2(sr[ic], si[ic]), make_float2(w2.x, -w2.y));
            float2 Dv = cmulf(make_float2(sr[id], si[id]), make_float2(w3.x, -w3.y));
            float2 t0 = f2add(A, Cv), t1 = f2sub(A, Cv);
            float2 t2 = f2add(Bv, Dv), t3 = f2sub(Bv, Dv);
            float2 r0 = f2add(t0, t2);
            float2 r1 = make_float2(t1.x - t3.y, t1.y + t3.x);
            float2 r2 = f2sub(t0, t2);
            float2 r3 = make_float2(t1.x + t3.y, t1.y - t3.x);
            sr[ia] = r0.x; si[ia] = r0.y;
            sr[ib] = r1.x; si[ib] = r1.y;
            sr[ic] = r2.x; si[ic] = r2.y;
            sr[id] = r3.x; si[id] = r3.y;
        }
        __syncthreads();
    }

    float* ph0 = g_phase + (size_t)(2 * blockIdx.x) * TT;
    float* ph1 = ph0 + TT;
    for (int t = tid; t < TT; t += 512) {
        const int ip = PIDX(t);
        ph0[t] = atan2f(sr[ip], 4096.0f * x0[t]);
        ph1[t] = atan2f(si[ip], 4096.0f * x1[t]);
    }
}

// ---------------- kernel 2: fused features + HMMA GEMM + argmin ----------
__device__ __forceinline__ void prefetch_chunk(uint32_t sdst, int ch, int tid) {
    const char* src = (const char*)g_B + (size_t)ch * CROWS * 256;
#pragma unroll
    for (int it = 0; it < 4; ++it) {
        const int i = tid + it * 256;       // 1024 uint4 total
        const int r = i >> 4, kq = i & 15;
        CP_ASYNC16(sdst + (uint32_t)r * KP_B + (uint32_t)kq * 16u,
                   src + (size_t)r * 256 + (size_t)kq * 16);
    }
    CP_COMMIT();
}

__global__ void __launch_bounds__(256, 2)
quant_kernel(const float* __restrict__ imu,
             const float* __restrict__ Wm,
             const float* __restrict__ bm,
             const float* __restrict__ Wp,
             const float* __restrict__ bp,
             const float* __restrict__ cb,
             float* __restrict__ out) {
    extern __shared__ char smem[];
    const uint32_t sbase = smem_to_u32(smem);
    const int tid = threadIdx.x;
    const int wid = tid >> 5;
    const int lane = tid & 31;
    const int pbase = blockIdx.x * MBLK;

    float* scn = (float*)(smem + SM_CN);
    float* rbv = (float*)(smem + SM_RBV);
    int* rbi = (int*)(smem + SM_RBI);
    int* sidx = (int*)(smem + SM_IDX);

    // start B pipeline before the heavy feature phase (buffers 0, 1)
    prefetch_chunk(sbase + SM_B0, 0, tid);
    prefetch_chunk(sbase + SM_B0 + 17408u, 1, tid);

    for (int i = tid; i < NC; i += 256) scn[i] = g_cn[i];

    // ---- features for 128 positions -> SMEM A (bf16 hi|lo)
    if (tid < MBLK) {
        const int p = pbase + tid;
        const int b = p >> 12;
        const int t = p & (TT - 1);

        const float* xb = imu + (size_t)b * CC * TT + t;
        float xc[9];
#pragma unroll
        for (int c = 0; c < 9; ++c) xc[c] = xb[c * TT];

        const float* phb = g_phase + (size_t)b * CC * TT + t;
        float pm = 0.0f;
#pragma unroll
        for (int c = 0; c < 9; ++c) pm += phb[c * TT];
        pm *= (1.0f / 9.0f);
        float sp, cp;
        sincosf(pm, &sp, &cp);
        out[OFF_PH + p] = pm;

        float f[64];
#pragma unroll
        for (int i = 0; i < 32; ++i) {
            float a = bm[i];
#pragma unroll
            for (int c = 0; c < 9; ++c) a += Wm[i * 9 + c] * xc[c];
            f[i] = a;
        }
        float comb[9];
#pragma unroll
        for (int c = 0; c < 7; ++c) comb[c] = xc[c];
        comb[7] = cp;
        comb[8] = sp;
#pragma unroll
        for (int i = 0; i < 32; ++i) {
            float a = bp[i];
#pragma unroll
            for (int c = 0; c < 9; ++c) a += Wp[i * 9 + c] * comb[c];
            f[32 + i] = a;
        }

        uint32_t* row32 = (uint32_t*)(smem + SM_A + (uint32_t)tid * KP_B);
#pragma unroll
        for (int q = 0; q < 32; ++q) {
            uint32_t hp, lp;
            split_pack(f[2 * q], f[2 * q + 1], hp, lp);
            row32[q] = hp;            // f_hi (bytes 0..127)
            row32[32 + q] = lp;       // f_lo (bytes 128..255)
        }
    }
    __syncthreads();   // A + cn visible

    // ---- GEMM + argmin. Warp tile m32 x n32: 4 m-warps x 2 n-warps.
    const int wrow = wid & 3;
    const int wcol = wid >> 2;
    const int m0 = wrow * 32;

    float best[4];
    int bidx[4];
#pragma unroll
    for (int i = 0; i < 4; ++i) { best[i] = CUDART_INF_F; bidx[i] = 0; }

    const int mgrp = lane >> 3;     // 0..3
    const int mrow = lane & 7;
    const uint32_t a_base = sbase + SM_A
        + (uint32_t)(m0 + mrow + 8 * (mgrp & 1)) * KP_B
        + (uint32_t)(8 * (mgrp >> 1)) * 2u;
    const uint32_t b_base = (uint32_t)(wcol * 32) * KP_B
        + (uint32_t)(8 * (mgrp >> 1) + mrow) * KP_B
        + (uint32_t)(8 * (mgrp & 1)) * 2u;

    // ---- A fragments register-resident: [mt][kquad][hi/lo][4] = 64 regs
    uint32_t afr[2][4][2][4];
#pragma unroll
    for (int mt = 0; mt < 2; ++mt)
#pragma unroll
        for (int kq = 0; kq < 4; ++kq) {
            const uint32_t ab = a_base + (uint32_t)mt * (16u * KP_B)
                                + (uint32_t)kq * 32u;
            LDSM_X4(afr[mt][kq][0][0], afr[mt][kq][0][1],
                    afr[mt][kq][0][2], afr[mt][kq][0][3], ab);
            LDSM_X4(afr[mt][kq][1][0], afr[mt][kq][1][1],
                    afr[mt][kq][1][2], afr[mt][kq][1][3], ab + 128u);
        }

#pragma unroll 1
    for (int ch = 0; ch < 8; ++ch) {
        if (ch < 7) { CP_WAIT(1); } else { CP_WAIT(0); }
        __syncthreads();            // chunk ch buffer complete; all warps past ch-1

        // prefetch ch+2 into ring buffer (ch+2)%3 — not read until chunk ch+2
        if (ch < 6)
            prefetch_chunk(sbase + SM_B0 + (uint32_t)((ch + 2) % 3) * 17408u,
                           ch + 2, tid);

        const uint32_t sB = sbase + SM_B0 + (uint32_t)(ch % 3) * 17408u;

        float acc[2][4][4];
#pragma unroll
        for (int mt = 0; mt < 2; ++mt)
#pragma unroll
            for (int j = 0; j < 4; ++j)
#pragma unroll
                for (int q = 0; q < 4; ++q) acc[mt][j][q] = 0.0f;

        // acc += A_hi*B_hi + A_lo*B_hi + A_hi*B_lo  (4 k-quads of 16)
#pragma unroll
        for (int kq = 0; kq < 4; ++kq) {
            const uint32_t koff = (uint32_t)kq * 32u;
            {   // n-tile 0
                uint32_t bh[4], bl[4];
                LDSM_X4(bh[0], bh[1], bh[2], bh[3], sB + b_base + koff);
                LDSM_X4(bl[0], bl[1], bl[2], bl[3], sB + b_base + 128u + koff);
                MMA16816(acc[0][0], afr[0][kq][0], bh[0], bh[1]);
                MMA16816(acc[0][1], afr[0][kq][0], bh[2], bh[3]);
                MMA16816(acc[1][0], afr[1][kq][0], bh[0], bh[1]);
                MMA16816(acc[1][1], afr[1][kq][0], bh[2], bh[3]);
                MMA16816(acc[0][0], afr[0][kq][1], bh[0], bh[1]);
                MMA16816(acc[0][1], afr[0][kq][1], bh[2], bh[3]);
                MMA16816(acc[1][0], afr[1][kq][1], bh[0], bh[1]);
                MMA16816(acc[1][1], afr[1][kq][1], bh[2], bh[3]);
                MMA16816(acc[0][0], afr[0][kq][0], bl[0], bl[1]);
                MMA16816(acc[0][1], afr[0][kq][0], bl[2], bl[3]);
                MMA16816(acc[1][0], afr[1][kq][0], bl[0], bl[1]);
                MMA16816(acc[1][1], afr[1][kq][0], bl[2], bl[3]);
            }
            {   // n-tile 1
                uint32_t bh[4], bl[4];
                LDSM_X4(bh[0], bh[1], bh[2], bh[3],
                        sB + b_base + 16u * KP_B + koff);
                LDSM_X4(bl[0], bl[1], bl[2], bl[3],
                        sB + b_base + 16u * KP_B + 128u + koff);
                MMA16816(acc[0][2], afr[0][kq][0], bh[0], bh[1]);
                MMA16816(acc[0][3], afr[0][kq][0], bh[2], bh[3]);
                MMA16816(acc[1][2], afr[1][kq][0], bh[0], bh[1]);
                MMA16816(acc[1][3], afr[1][kq][0], bh[2], bh[3]);
                MMA16816(acc[0][2], afr[0][kq][1], bh[0], bh[1]);
                MMA16816(acc[0][3], afr[0][kq][1], bh[2], bh[3]);
                MMA16816(acc[1][2], afr[1][kq][1], bh[0], bh[1]);
                MMA16816(acc[1][3], afr[1][kq][1], bh[2], bh[3]);
                MMA16816(acc[0][2], afr[0][kq][0], bl[0], bl[1]);
                MMA16816(acc[0][3], afr[0][kq][0], bl[2], bl[3]);
                MMA16816(acc[1][2], afr[1][kq][0], bl[0], bl[1]);
                MMA16816(acc[1][3], afr[1][kq][0], bl[2], bl[3]);
            }
        }

        // running argmin (codes strictly increasing -> first-min kept)
#pragma unroll
        for (int mt = 0; mt < 2; ++mt)
#pragma unroll
            for (int j = 0; j < 4; ++j) {
                const int c0 = ch * CROWS + wcol * 32 + (j >> 1) * 16
                               + (j & 1) * 8 + (lane & 3) * 2;
                const float n0v = scn[c0], n1v = scn[c0 + 1];
                const float d0 = fmaf(-2.0f, acc[mt][j][0], n0v);
                const float d1 = fmaf(-2.0f, acc[mt][j][1], n1v);
                const float d2 = fmaf(-2.0f, acc[mt][j][2], n0v);
                const float d3 = fmaf(-2.0f, acc[mt][j][3], n1v);
                const int s0 = 2 * mt, s1 = 2 * mt + 1;
                if (d0 < best[s0]) { best[s0] = d0; bidx[s0] = c0; }
                if (d1 < best[s0]) { best[s0] = d1; bidx[s0] = c0 + 1; }
                if (d2 < best[s1]) { best[s1] = d2; bidx[s1] = c0; }
                if (d3 < best[s1]) { best[s1] = d3; bidx[s1] = c0 + 1; }
            }
    }

    // reduce across the 4 lanes sharing each row (quad)
#pragma unroll
    for (int off = 1; off <= 2; off <<= 1) {
#pragma unroll
        for (int s = 0; s < 4; ++s) {
            float ob = __shfl_xor_sync(0xffffffffu, best[s], off);
            int oi = __shfl_xor_sync(0xffffffffu, bidx[s], off);
            if (ob < best[s] || (ob == best[s] && oi < bidx[s])) {
                best[s] = ob; bidx[s] = oi;
            }
        }
    }
    if ((lane & 3) == 0) {
        const int r = lane >> 2;
#pragma unroll
        for (int mt = 0; mt < 2; ++mt)
#pragma unroll
            for (int h = 0; h < 2; ++h) {
                const int row = m0 + mt * 16 + 8 * h + r;
                rbv[row * 2 + wcol] = best[2 * mt + h];
                rbi[row * 2 + wcol] = bidx[2 * mt + h];
            }
    }
    __syncthreads();

    // cross-nwarp reduce: one thread per row
    if (tid < MBLK) {
        float bv = rbv[tid * 2];
        int bi = rbi[tid * 2];
        const float ov = rbv[tid * 2 + 1];
        const int oi = rbi[tid * 2 + 1];
        if (ov < bv || (ov == bv && oi < bi)) { bv = ov; bi = oi; }
        sidx[tid] = bi;
        out[OFF_IDX + pbase + tid] = (float)bi;
    }
    __syncthreads();

    // quantized rows from fp32 codebook (L2-hot)
    const float4* cb4 = (const float4*)cb;
    for (int q = tid; q < MBLK * (CD / 4); q += 256) {
        const int pos = q >> 4;
        const int w = q & 15;
        ((float4*)(out + (size_t)(pbase + pos) * CD))[w] =
            cb4[(size_t)sidx[pos] * (CD / 4) + w];
    }
}

// ---------------- launch ----------------
extern "C" void kernel_launch(void* const* d_in, const int* in_sizes, int n_in,
                              void* d_out, int out_size) {
    const float* imu = (const float*)d_in[0];
    const float* Wm  = (const float*)d_in[1];
    const float* bm  = (const float*)d_in[2];
    const float* Wp  = (const float*)d_in[3];
    const float* bp  = (const float*)d_in[4];
    const float* cb  = (const float*)d_in[5];
    float* out = (float*)d_out;

    cudaFuncSetAttribute(fft_conv_kernel,
                         cudaFuncAttributeMaxDynamicSharedMemorySize, FFT_SMEM);
    fft_conv_kernel<<<NPAIR + NC / 16, 512, FFT_SMEM>>>(imu, cb);

    cudaFuncSetAttribute(quant_kernel,
                         cudaFuncAttributeMaxDynamicSharedMemorySize, SMEMSZ);
    quant_kernel<<<(BB * TT) / MBLK, 256, SMEMSZ>>>(imu, Wm, bm, Wp, bp, cb, out);
}

// round 14
// speedup vs baseline: 1.8160x; 1.8160x over previous
#include <cuda_runtime.h>
#include <cuda_bf16.h>
#include <math_constants.h>
#include <cstdint>

#define BB 32
#define CC 9
#define TT 4096
#define NC 512
#define CD 64
#define MBLK 128          // positions per block
#define KP_B 112          // SMEM row stride bytes (3x32B segments + 16 pad)
#define CROWS 64          // codes per argmin chunk (8 chunks, B fully resident)
#define NROWS (BB * CC)   // 288 real rows
#define NPAIR (NROWS / 2) // 144 packed FFTs

#define OFF_IDX ((size_t)BB * TT * CD)
#define OFF_PH  (OFF_IDX + (size_t)BB * TT)

// SMEM map for quant kernel (bytes)
#define SM_A    0u        // 128 * 112 = 14336
#define SM_B    14336u    // 512 * 112 = 57344
#define SM_CN   71680u    // 2048
#define SM_RBV  73728u    // float [128][2]
#define SM_RBI  74752u    // int   [128][2]
#define SM_IDX  75776u    // int   [128]
#define SMEMSZ  76288     // 2 CTAs/SM

#define FFT_SMEM (4 * TT * 4)   // float2 s[4096] + float2 tw[4096] = 64 KB

// ---------------- global scratch ----------------
__device__ float g_phase[BB * CC * TT];
__device__ __align__(16) __nv_bfloat16 g_B[NC * 48];  // per code: hi|hi|lo segs of 16
__device__ float g_cn[NC];                            // ||c||^2 - 2*b.c

__device__ __forceinline__ uint32_t smem_to_u32(const void* p) {
    uint32_t a;
    asm("{ .reg .u64 t; cvta.to.shared.u64 t, %1; cvt.u32.u64 %0, t; }"
        : "=r"(a) : "l"(p));
    return a;
}

#define LDSM_X4(r0, r1, r2, r3, addr) \
    asm volatile("ldmatrix.sync.aligned.m8n8.x4.shared.b16 {%0,%1,%2,%3}, [%4];" \
                 : "=r"(r0), "=r"(r1), "=r"(r2), "=r"(r3) : "r"(addr))

#define MMA16816(d, a, b0, b1) \
    asm volatile("mma.sync.aligned.m16n8k16.row.col.f32.bf16.bf16.f32 " \
                 "{%0,%1,%2,%3}, {%4,%5,%6,%7}, {%8,%9}, {%0,%1,%2,%3};" \
                 : "+f"((d)[0]), "+f"((d)[1]), "+f"((d)[2]), "+f"((d)[3]) \
                 : "r"((a)[0]), "r"((a)[1]), "r"((a)[2]), "r"((a)[3]), \
                   "r"(b0), "r"(b1))

#define CP_ASYNC16(saddr, gptr) \
    asm volatile("cp.async.cg.shared.global [%0], [%1], 16;" \
                 :: "r"(saddr), "l"(gptr) : "memory")
#define CP_COMMIT() asm volatile("cp.async.commit_group;" ::: "memory")
#define CP_WAIT(n)  asm volatile("cp.async.wait_group %0;" :: "n"(n) : "memory")

__device__ __forceinline__ float2 cmulf(float2 a, float2 b) {
    return make_float2(a.x * b.x - a.y * b.y, a.x * b.y + a.y * b.x);
}
__device__ __forceinline__ float2 f2add(float2 a, float2 b) {
    return make_float2(a.x + b.x, a.y + b.y);
}
__device__ __forceinline__ float2 f2sub(float2 a, float2 b) {
    return make_float2(a.x - b.x, a.y - b.y);
}

__device__ __forceinline__ void split_pack(float v0, float v1,
                                           uint32_t& hp, uint32_t& lp) {
    __nv_bfloat16 h0 = __float2bfloat16(v0), h1 = __float2bfloat16(v1);
    __nv_bfloat16 l0 = __float2bfloat16(v0 - __bfloat162float(h0));
    __nv_bfloat16 l1 = __float2bfloat16(v1 - __bfloat162float(h1));
    hp = ((uint32_t)__bfloat16_as_ushort(h1) << 16) | __bfloat16_as_ushort(h0);
    lp = ((uint32_t)__bfloat16_as_ushort(l1) << 16) | __bfloat16_as_ushort(l0);
}

// ---------------- kernel 1: packed Hilbert FFT + codebook projection ----
// blocks [0, NPAIR): two real rows packed as one complex FFT (512 thr).
// blocks [NPAIR, NPAIR+32): per-code projection c -> (W~^T c, ||c||^2-2 b.c).
__global__ void fft_conv_kernel(const float* __restrict__ imu,
                                const float* __restrict__ cb,
                                const float* __restrict__ Wm,
                                const float* __restrict__ bm,
                                const float* __restrict__ Wp,
                                const float* __restrict__ bp) {
    const int tid = threadIdx.x;

    if (blockIdx.x >= NPAIR) {
        // ---- codebook projection: warp per code (16 warps per block) ----
        const int wid = tid >> 5, lane = tid & 31;
        const int c = (blockIdx.x - NPAIR) * 16 + wid;
        const float cl = cb[(size_t)c * CD + lane];        // c[lane]
        const float chn = cb[(size_t)c * CD + 32 + lane];  // c[32+lane]

        float red[20];
#pragma unroll
        for (int j = 0; j < 9; ++j) {
            red[j]     = Wm[lane * 9 + j] * cl;
            red[9 + j] = Wp[lane * 9 + j] * chn;
        }
        red[18] = bm[lane] * cl + bp[lane] * chn;          // b.c partial
        red[19] = cl * cl + chn * chn;                     // norm partial
#pragma unroll
        for (int off = 16; off >= 1; off >>= 1)
#pragma unroll
            for (int v = 0; v < 20; ++v)
                red[v] += __shfl_xor_sync(0xffffffffu, red[v], off);

        if (lane == 0) {
            float e[12];
#pragma unroll
            for (int j = 0; j < 7; ++j) e[j] = red[j] + red[9 + j];
            e[7] = red[7];  e[8] = red[8];
            e[9] = red[16]; e[10] = red[17];
            e[11] = 0.0f;
            uint32_t hi[6], lo[6];
#pragma unroll
            for (int q = 0; q < 6; ++q)
                split_pack(e[2 * q], e[2 * q + 1], hi[q], lo[q]);
            uint32_t* row32 = (uint32_t*)(g_B + (size_t)c * 48);
#pragma unroll
            for (int q = 0; q < 6; ++q) {
                row32[q] = hi[q];           // seg0: c_hi
                row32[8 + q] = hi[q];       // seg1: c_hi
                row32[16 + q] = lo[q];      // seg2: c_lo
            }
            row32[6] = 0u; row32[7] = 0u;
            row32[14] = 0u; row32[15] = 0u;
            row32[22] = 0u; row32[23] = 0u;
            g_cn[c] = red[19] - 2.0f * red[18];
        }
        return;
    }

    extern __shared__ float2 dsh[];
    float2* s = dsh;            // 4096
    float2* tw = dsh + TT;      // 4096: tw[k] = exp(-2*pi*i*k/4096)
    const float* x0 = imu + (size_t)(2 * blockIdx.x) * TT;
    const float* x1 = x0 + TT;

    for (int k = tid; k < TT; k += 512) {
        float sn, cs;
        sincosf(-(float)CUDART_PI_F * (float)k / 2048.0f, &sn, &cs);
        tw[k] = make_float2(cs, sn);
    }
    for (int t = tid; t < TT; t += 512)
        s[t] = make_float2(x0[t], x1[t]);
    __syncthreads();

    // Forward radix-4 DIF: natural in, base-4 digit-reversed out.
#pragma unroll
    for (int ls = 10; ls >= 0; ls -= 2) {
        const int L = 1 << ls;
        const int m = 1024 >> ls;
        for (int i = tid; i < 1024; i += 512) {
            const int j = i & (L - 1);
            const int i0 = ((i >> ls) << (ls + 2)) + j;
            float2 a = s[i0], b = s[i0 + L], c = s[i0 + 2 * L], d = s[i0 + 3 * L];
            float2 t0 = f2add(a, c), t1 = f2sub(a, c);
            float2 t2 = f2add(b, d), t3 = f2sub(b, d);
            s[i0] = f2add(t0, t2);
            s[i0 + L] = cmulf(make_float2(t1.x + t3.y, t1.y - t3.x), tw[j * m]);
            s[i0 + 2 * L] = cmulf(f2sub(t0, t2), tw[2 * j * m]);
            s[i0 + 3 * L] = cmulf(make_float2(t1.x - t3.y, t1.y + t3.x), tw[3 * j * m]);
        }
        __syncthreads();
    }

    // Hilbert multiplier M[k] = -i*sgn(k) at base-4 digit-reversed slot.
    for (int p = tid; p < TT; p += 512) {
        const int r = (int)(__brev((unsigned)p) >> 20);
        const int k = ((r & 0x555) << 1) | ((r >> 1) & 0x555);
        float2 v = s[p];
        if (k == 0 || k == TT / 2)  s[p] = make_float2(0.0f, 0.0f);
        else if (k < TT / 2)        s[p] = make_float2(v.y, -v.x);
        else                        s[p] = make_float2(-v.y, v.x);
    }
    __syncthreads();

    // Inverse radix-4 DIT: digit-reversed in, natural out (conj twiddles, no 1/N).
#pragma unroll
    for (int ls = 0; ls <= 10; ls += 2) {
        const int L = 1 << ls;
        const int m = 1024 >> ls;
        for (int i = tid; i < 1024; i += 512) {
            const int j = i & (L - 1);
            const int i0 = ((i >> ls) << (ls + 2)) + j;
            float2 w1 = tw[j * m], w2 = tw[2 * j * m], w3 = tw[3 * j * m];
            float2 A = s[i0];
            float2 Bv = cmulf(s[i0 + L],     make_float2(w1.x, -w1.y));
            float2 Cv = cmulf(s[i0 + 2 * L], make_float2(w2.x, -w2.y));
            float2 Dv = cmulf(s[i0 + 3 * L], make_float2(w3.x, -w3.y));
            float2 t0 = f2add(A, Cv), t1 = f2sub(A, Cv);
            float2 t2 = f2add(Bv, Dv), t3 = f2sub(Bv, Dv);
            s[i0] = f2add(t0, t2);
            s[i0 + L] = make_float2(t1.x - t3.y, t1.y + t3.x);
            s[i0 + 2 * L] = f2sub(t0, t2);
            s[i0 + 3 * L] = make_float2(t1.x + t3.y, t1.y - t3.x);
        }
        __syncthreads();
    }

    float* ph0 = g_phase + (size_t)(2 * blockIdx.x) * TT;
    float* ph1 = ph0 + TT;
    for (int t = tid; t < TT; t += 512) {
        const float2 v = s[t];
        ph0[t] = atan2f(v.x, 4096.0f * x0[t]);
        ph1[t] = atan2f(v.y, 4096.0f * x1[t]);
    }
}

// ---------------- kernel 2: u-projection + K=48 HMMA GEMM + argmin ----------
__global__ void __launch_bounds__(256, 2)
quant_kernel(const float* __restrict__ imu,
             const float* __restrict__ cb,
             float* __restrict__ out) {
    extern __shared__ char smem[];
    const uint32_t sbase = smem_to_u32(smem);
    const int tid = threadIdx.x;
    const int wid = tid >> 5;
    const int lane = tid & 31;
    const int pbase = blockIdx.x * MBLK;

    float* scn = (float*)(smem + SM_CN);
    float* rbv = (float*)(smem + SM_RBV);
    int* rbi = (int*)(smem + SM_RBI);
    int* sidx = (int*)(smem + SM_IDX);

    // prefetch the WHOLE projected codebook: 512 rows x 96 B = 3072 uint4
    {
        const char* src = (const char*)g_B;
#pragma unroll
        for (int it = 0; it < 12; ++it) {
            const int i = tid + it * 256;
            const int r = i / 6, q = i - r * 6;
            CP_ASYNC16(sbase + SM_B + (uint32_t)r * KP_B + (uint32_t)q * 16u,
                       src + (size_t)r * 96 + (size_t)q * 16);
        }
        CP_COMMIT();
    }

    for (int i = tid; i < NC; i += 256) scn[i] = g_cn[i];

    // ---- u-vector for 128 positions -> SMEM A (bf16 hi|lo|hi segments)
    if (tid < MBLK) {
        const int p = pbase + tid;
        const int b = p >> 12;
        const int t = p & (TT - 1);

        const float* xb = imu + (size_t)b * CC * TT + t;
        float u[12];
#pragma unroll
        for (int c = 0; c < 9; ++c) u[c] = xb[c * TT];

        const float* phb = g_phase + (size_t)b * CC * TT + t;
        float pm = 0.0f;
#pragma unroll
        for (int c = 0; c < 9; ++c) pm += phb[c * TT];
        pm *= (1.0f / 9.0f);
        float sp, cp;
        sincosf(pm, &sp, &cp);
        out[OFF_PH + p] = pm;
        u[9] = cp;
        u[10] = sp;
        u[11] = 0.0f;

        uint32_t* row32 = (uint32_t*)(smem + SM_A + (uint32_t)tid * KP_B);
#pragma unroll
        for (int q = 0; q < 6; ++q) {
            uint32_t hp, lp;
            split_pack(u[2 * q], u[2 * q + 1], hp, lp);
            row32[q] = hp;            // seg0: u_hi
            row32[8 + q] = lp;        // seg1: u_lo
            row32[16 + q] = hp;       // seg2: u_hi
        }
        row32[6] = 0u; row32[7] = 0u;
        row32[14] = 0u; row32[15] = 0u;
        row32[22] = 0u; row32[23] = 0u;
    }
    CP_WAIT(0);
    __syncthreads();   // A + B + cn all visible; no more barriers until epilogue

    // ---- GEMM + argmin. Warp tile m32 x n32: 4 m-warps x 2 n-warps.
    const int wrow = wid & 3;
    const int wcol = wid >> 2;
    const int m0 = wrow * 32;

    float best[4];
    int bidx[4];
#pragma unroll
    for (int i = 0; i < 4; ++i) { best[i] = CUDART_INF_F; bidx[i] = 0; }

    const int mgrp = lane >> 3;     // 0..3
    const int mrow = lane & 7;
    const uint32_t a_base = sbase + SM_A
        + (uint32_t)(m0 + mrow + 8 * (mgrp & 1)) * KP_B
        + (uint32_t)(8 * (mgrp >> 1)) * 2u;
    const uint32_t b_row_off = (uint32_t)(8 * (mgrp >> 1) + mrow) * KP_B
        + (uint32_t)(8 * (mgrp & 1)) * 2u;

    // ---- A fragments register-resident: [mt][kstep][4] = 24 regs
    uint32_t afr[2][3][4];
#pragma unroll
    for (int mt = 0; mt < 2; ++mt)
#pragma unroll
        for (int k = 0; k < 3; ++k)
            LDSM_X4(afr[mt][k][0], afr[mt][k][1], afr[mt][k][2], afr[mt][k][3],
                    a_base + (uint32_t)mt * (16u * KP_B) + (uint32_t)k * 32u);

#pragma unroll 1
    for (int ch = 0; ch < 8; ++ch) {
        const uint32_t sBc = sbase + SM_B + (uint32_t)ch * (CROWS * KP_B);

        float acc[2][4][4];
#pragma unroll
        for (int mt = 0; mt < 2; ++mt)
#pragma unroll
            for (int j = 0; j < 4; ++j)
#pragma unroll
                for (int q = 0; q < 4; ++q) acc[mt][j][q] = 0.0f;

#pragma unroll
        for (int nt = 0; nt < 2; ++nt) {
            const uint32_t bb = sBc + (uint32_t)(wcol * 32 + nt * 16) * KP_B
                                + b_row_off;
            uint32_t bq[3][4];
#pragma unroll
            for (int k = 0; k < 3; ++k)
                LDSM_X4(bq[k][0], bq[k][1], bq[k][2], bq[k][3],
                        bb + (uint32_t)k * 32u);
#pragma unroll
            for (int k = 0; k < 3; ++k) {
                MMA16816(acc[0][2 * nt],     afr[0][k], bq[k][0], bq[k][1]);
                MMA16816(acc[0][2 * nt + 1], afr[0][k], bq[k][2], bq[k][3]);
                MMA16816(acc[1][2 * nt],     afr[1][k], bq[k][0], bq[k][1]);
                MMA16816(acc[1][2 * nt + 1], afr[1][k], bq[k][2], bq[k][3]);
            }
        }

        // running argmin (codes strictly increasing -> first-min kept)
#pragma unroll
        for (int mt = 0; mt < 2; ++mt)
#pragma unroll
            for (int j = 0; j < 4; ++j) {
                const int c0 = ch * CROWS + wcol * 32 + (j >> 1) * 16
                               + (j & 1) * 8 + (lane & 3) * 2;
                const float n0v = scn[c0], n1v = scn[c0 + 1];
                const float d0 = fmaf(-2.0f, acc[mt][j][0], n0v);
                const float d1 = fmaf(-2.0f, acc[mt][j][1], n1v);
                const float d2 = fmaf(-2.0f, acc[mt][j][2], n0v);
                const float d3 = fmaf(-2.0f, acc[mt][j][3], n1v);
                const int s0 = 2 * mt, s1 = 2 * mt + 1;
                if (d0 < best[s0]) { best[s0] = d0; bidx[s0] = c0; }
                if (d1 < best[s0]) { best[s0] = d1; bidx[s0] = c0 + 1; }
                if (d2 < best[s1]) { best[s1] = d2; bidx[s1] = c0; }
                if (d3 < best[s1]) { best[s1] = d3; bidx[s1] = c0 + 1; }
            }
    }

    // reduce across the 4 lanes sharing each row (quad)
#pragma unroll
    for (int off = 1; off <= 2; off <<= 1) {
#pragma unroll
        for (int s = 0; s < 4; ++s) {
            float ob = __shfl_xor_sync(0xffffffffu, best[s], off);
            int oi = __shfl_xor_sync(0xffffffffu, bidx[s], off);
            if (ob < best[s] || (ob == best[s] && oi < bidx[s])) {
                best[s] = ob; bidx[s] = oi;
            }
        }
    }
    if ((lane & 3) == 0) {
        const int r = lane >> 2;
#pragma unroll
        for (int mt = 0; mt < 2; ++mt)
#pragma unroll
            for (int h = 0; h < 2; ++h) {
                const int row = m0 + mt * 16 + 8 * h + r;
                rbv[row * 2 + wcol] = best[2 * mt + h];
                rbi[row * 2 + wcol] = bidx[2 * mt + h];
            }
    }
    __syncthreads();

    // cross-nwarp reduce: one thread per row
    if (tid < MBLK) {
        float bv = rbv[tid * 2];
        int bi = rbi[tid * 2];
        const float ov = rbv[tid * 2 + 1];
        const int oi = rbi[tid * 2 + 1];
        if (ov < bv || (ov == bv && oi < bi)) { bv = ov; bi = oi; }
        sidx[tid] = bi;
        out[OFF_IDX + pbase + tid] = (float)bi;
    }
    __syncthreads();

    // quantized rows from fp32 codebook (L2-hot)
    const float4* cb4 = (const float4*)cb;
    for (int q = tid; q < MBLK * (CD / 4); q += 256) {
        const int pos = q >> 4;
        const int w = q & 15;
        ((float4*)(out + (size_t)(pbase + pos) * CD))[w] =
            cb4[(size_t)sidx[pos] * (CD / 4) + w];
    }
}

// ---------------- launch ----------------
extern "C" void kernel_launch(void* const* d_in, const int* in_sizes, int n_in,
                              void* d_out, int out_size) {
    const float* imu = (const float*)d_in[0];
    const float* Wm  = (const float*)d_in[1];
    const float* bm  = (const float*)d_in[2];
    const float* Wp  = (const float*)d_in[3];
    const float* bp  = (const float*)d_in[4];
    const float* cb  = (const float*)d_in[5];
    float* out = (float*)d_out;

    cudaFuncSetAttribute(fft_conv_kernel,
                         cudaFuncAttributeMaxDynamicSharedMemorySize, FFT_SMEM);
    fft_conv_kernel<<<NPAIR + NC / 16, 512, FFT_SMEM>>>(imu, cb, Wm, bm, Wp, bp);

    cudaFuncSetAttribute(quant_kernel,
                         cudaFuncAttributeMaxDynamicSharedMemorySize, SMEMSZ);
    quant_kernel<<<(BB * TT) / MBLK, 256, SMEMSZ>>>(imu, cb, out);
}

// round 15
// speedup vs baseline: 1.8763x; 1.0332x over previous
#include <cuda_runtime.h>
#include <cuda_bf16.h>
#include <math_constants.h>
#include <cstdint>

#define BB 32
#define CC 9
#define TT 4096
#define NC 512
#define CD 64
#define MBLK 256          // positions per block
#define KP_B 112          // SMEM row stride bytes (3x32B segments + 16 pad)
#define NROWS (BB * CC)   // 288 real rows
#define NPAIR (NROWS / 2) // 144 packed FFTs

#define OFF_IDX ((size_t)BB * TT * CD)
#define OFF_PH  (OFF_IDX + (size_t)BB * TT)

// SMEM map for quant kernel (bytes)
#define SM_A    0u        // 256 * 112 = 28672
#define SM_B    28672u    // 512 * 112 = 57344
#define SM_CN   86016u    // 2048
#define SM_IDX  88064u    // 1024
#define SMEMSZ  89088     // 2 CTAs/SM

#define FFT_SMEM (4 * TT * 4)   // float2 s[4096] + float2 tw[4096] = 64 KB

// ---------------- global scratch ----------------
__device__ float g_phase[BB * CC * TT];
__device__ __align__(16) __nv_bfloat16 g_B[NC * 48];  // per code: hi|hi|lo segs of 16
__device__ float g_cn[NC];                            // ||c||^2 - 2*b.c

__device__ __forceinline__ uint32_t smem_to_u32(const void* p) {
    uint32_t a;
    asm("{ .reg .u64 t; cvta.to.shared.u64 t, %1; cvt.u32.u64 %0, t; }"
        : "=r"(a) : "l"(p));
    return a;
}

#define LDSM_X4(r0, r1, r2, r3, addr) \
    asm volatile("ldmatrix.sync.aligned.m8n8.x4.shared.b16 {%0,%1,%2,%3}, [%4];" \
                 : "=r"(r0), "=r"(r1), "=r"(r2), "=r"(r3) : "r"(addr))

#define MMA16816(d, a, b0, b1) \
    asm volatile("mma.sync.aligned.m16n8k16.row.col.f32.bf16.bf16.f32 " \
                 "{%0,%1,%2,%3}, {%4,%5,%6,%7}, {%8,%9}, {%0,%1,%2,%3};" \
                 : "+f"((d)[0]), "+f"((d)[1]), "+f"((d)[2]), "+f"((d)[3]) \
                 : "r"((a)[0]), "r"((a)[1]), "r"((a)[2]), "r"((a)[3]), \
                   "r"(b0), "r"(b1))

#define CP_ASYNC16(saddr, gptr) \
    asm volatile("cp.async.cg.shared.global [%0], [%1], 16;" \
                 :: "r"(saddr), "l"(gptr) : "memory")
#define CP_COMMIT() asm volatile("cp.async.commit_group;" ::: "memory")
#define CP_WAIT(n)  asm volatile("cp.async.wait_group %0;" :: "n"(n) : "memory")

__device__ __forceinline__ float2 cmulf(float2 a, float2 b) {
    return make_float2(a.x * b.x - a.y * b.y, a.x * b.y + a.y * b.x);
}
__device__ __forceinline__ float2 f2add(float2 a, float2 b) {
    return make_float2(a.x + b.x, a.y + b.y);
}
__device__ __forceinline__ float2 f2sub(float2 a, float2 b) {
    return make_float2(a.x - b.x, a.y - b.y);
}

__device__ __forceinline__ void split_pack(float v0, float v1,
                                           uint32_t& hp, uint32_t& lp) {
    __nv_bfloat16 h0 = __float2bfloat16(v0), h1 = __float2bfloat16(v1);
    __nv_bfloat16 l0 = __float2bfloat16(v0 - __bfloat162float(h0));
    __nv_bfloat16 l1 = __float2bfloat16(v1 - __bfloat162float(h1));
    hp = ((uint32_t)__bfloat16_as_ushort(h1) << 16) | __bfloat16_as_ushort(h0);
    lp = ((uint32_t)__bfloat16_as_ushort(l1) << 16) | __bfloat16_as_ushort(l0);
}

// ---------------- kernel 1: packed Hilbert FFT + codebook projection ----
__global__ void fft_conv_kernel(const float* __restrict__ imu,
                                const float* __restrict__ cb,
                                const float* __restrict__ Wm,
                                const float* __restrict__ bm,
                                const float* __restrict__ Wp,
                                const float* __restrict__ bp) {
    const int tid = threadIdx.x;

    if (blockIdx.x >= NPAIR) {
        // ---- codebook projection: warp per code (16 warps per block) ----
        const int wid = tid >> 5, lane = tid & 31;
        const int c = (blockIdx.x - NPAIR) * 16 + wid;
        const float cl = cb[(size_t)c * CD + lane];
        const float chn = cb[(size_t)c * CD + 32 + lane];

        float red[20];
#pragma unroll
        for (int j = 0; j < 9; ++j) {
            red[j]     = Wm[lane * 9 + j] * cl;
            red[9 + j] = Wp[lane * 9 + j] * chn;
        }
        red[18] = bm[lane] * cl + bp[lane] * chn;
        red[19] = cl * cl + chn * chn;
#pragma unroll
        for (int off = 16; off >= 1; off >>= 1)
#pragma unroll
            for (int v = 0; v < 20; ++v)
                red[v] += __shfl_xor_sync(0xffffffffu, red[v], off);

        if (lane == 0) {
            float e[12];
#pragma unroll
            for (int j = 0; j < 7; ++j) e[j] = red[j] + red[9 + j];
            e[7] = red[7];  e[8] = red[8];
            e[9] = red[16]; e[10] = red[17];
            e[11] = 0.0f;
            uint32_t hi[6], lo[6];
#pragma unroll
            for (int q = 0; q < 6; ++q)
                split_pack(e[2 * q], e[2 * q + 1], hi[q], lo[q]);
            uint32_t* row32 = (uint32_t*)(g_B + (size_t)c * 48);
#pragma unroll
            for (int q = 0; q < 6; ++q) {
                row32[q] = hi[q];           // seg0: c_hi
                row32[8 + q] = hi[q];       // seg1: c_hi
                row32[16 + q] = lo[q];      // seg2: c_lo
            }
            row32[6] = 0u; row32[7] = 0u;
            row32[14] = 0u; row32[15] = 0u;
            row32[22] = 0u; row32[23] = 0u;
            g_cn[c] = red[19] - 2.0f * red[18];
        }
        return;
    }

    extern __shared__ float2 dsh[];
    float2* s = dsh;            // 4096
    float2* tw = dsh + TT;      // 4096
    const float* x0 = imu + (size_t)(2 * blockIdx.x) * TT;
    const float* x1 = x0 + TT;

    for (int k = tid; k < TT; k += 512) {
        float sn, cs;
        sincosf(-(float)CUDART_PI_F * (float)k / 2048.0f, &sn, &cs);
        tw[k] = make_float2(cs, sn);
    }
    for (int t = tid; t < TT; t += 512)
        s[t] = make_float2(x0[t], x1[t]);
    __syncthreads();

    // Forward radix-4 DIF: natural in, base-4 digit-reversed out.
#pragma unroll
    for (int ls = 10; ls >= 0; ls -= 2) {
        const int L = 1 << ls;
        const int m = 1024 >> ls;
        for (int i = tid; i < 1024; i += 512) {
            const int j = i & (L - 1);
            const int i0 = ((i >> ls) << (ls + 2)) + j;
            float2 a = s[i0], b = s[i0 + L], c = s[i0 + 2 * L], d = s[i0 + 3 * L];
            float2 t0 = f2add(a, c), t1 = f2sub(a, c);
            float2 t2 = f2add(b, d), t3 = f2sub(b, d);
            s[i0] = f2add(t0, t2);
            s[i0 + L] = cmulf(make_float2(t1.x + t3.y, t1.y - t3.x), tw[j * m]);
            s[i0 + 2 * L] = cmulf(f2sub(t0, t2), tw[2 * j * m]);
            s[i0 + 3 * L] = cmulf(make_float2(t1.x - t3.y, t1.y + t3.x), tw[3 * j * m]);
        }
        __syncthreads();
    }

    // Hilbert multiplier M[k] = -i*sgn(k) at base-4 digit-reversed slot.
    for (int p = tid; p < TT; p += 512) {
        const int r = (int)(__brev((unsigned)p) >> 20);
        const int k = ((r & 0x555) << 1) | ((r >> 1) & 0x555);
        float2 v = s[p];
        if (k == 0 || k == TT / 2)  s[p] = make_float2(0.0f, 0.0f);
        else if (k < TT / 2)        s[p] = make_float2(v.y, -v.x);
        else                        s[p] = make_float2(-v.y, v.x);
    }
    __syncthreads();

    // Inverse radix-4 DIT: digit-reversed in, natural out (conj twiddles, no 1/N).
#pragma unroll
    for (int ls = 0; ls <= 10; ls += 2) {
        const int L = 1 << ls;
        const int m = 1024 >> ls;
        for (int i = tid; i < 1024; i += 512) {
            const int j = i & (L - 1);
            const int i0 = ((i >> ls) << (ls + 2)) + j;
            float2 w1 = tw[j * m], w2 = tw[2 * j * m], w3 = tw[3 * j * m];
            float2 A = s[i0];
            float2 Bv = cmulf(s[i0 + L],     make_float2(w1.x, -w1.y));
            float2 Cv = cmulf(s[i0 + 2 * L], make_float2(w2.x, -w2.y));
            float2 Dv = cmulf(s[i0 + 3 * L], make_float2(w3.x, -w3.y));
            float2 t0 = f2add(A, Cv), t1 = f2sub(A, Cv);
            float2 t2 = f2add(Bv, Dv), t3 = f2sub(Bv, Dv);
            s[i0] = f2add(t0, t2);
            s[i0 + L] = make_float2(t1.x - t3.y, t1.y + t3.x);
            s[i0 + 2 * L] = f2sub(t0, t2);
            s[i0 + 3 * L] = make_float2(t1.x + t3.y, t1.y - t3.x);
        }
        __syncthreads();
    }

    float* ph0 = g_phase + (size_t)(2 * blockIdx.x) * TT;
    float* ph1 = ph0 + TT;
    for (int t = tid; t < TT; t += 512) {
        const float2 v = s[t];
        ph0[t] = atan2f(v.x, 4096.0f * x0[t]);
        ph1[t] = atan2f(v.y, 4096.0f * x1[t]);
    }
}

// ---------------- kernel 2: u-projection + K=48 HMMA GEMM + argmin ----------
// 512 threads, 16 m-warps (m16 each), whole B resident, barrier-free loop.
__global__ void __launch_bounds__(512, 2)
quant_kernel(const float* __restrict__ imu,
             const float* __restrict__ cb,
             float* __restrict__ out) {
    extern __shared__ char smem[];
    const uint32_t sbase = smem_to_u32(smem);
    const int tid = threadIdx.x;
    const int wid = tid >> 5;
    const int lane = tid & 31;
    const int pbase = blockIdx.x * MBLK;

    float* scn = (float*)(smem + SM_CN);
    int* sidx = (int*)(smem + SM_IDX);

    // prefetch the WHOLE projected codebook: 512 rows x 96 B = 3072 uint4
    {
        const char* src = (const char*)g_B;
#pragma unroll
        for (int it = 0; it < 6; ++it) {
            const int i = tid + it * 512;
            const int r = i / 6, q = i - r * 6;
            CP_ASYNC16(sbase + SM_B + (uint32_t)r * KP_B + (uint32_t)q * 16u,
                       src + (size_t)r * 96 + (size_t)q * 16);
        }
        CP_COMMIT();
    }

    for (int i = tid; i < NC; i += 512) scn[i] = g_cn[i];

    // ---- u-vector for 256 positions -> SMEM A (bf16 hi|lo|hi segments)
    if (tid < MBLK) {
        const int p = pbase + tid;
        const int b = p >> 12;
        const int t = p & (TT - 1);

        const float* xb = imu + (size_t)b * CC * TT + t;
        float u[12];
#pragma unroll
        for (int c = 0; c < 9; ++c) u[c] = xb[c * TT];

        const float* phb = g_phase + (size_t)b * CC * TT + t;
        float pm = 0.0f;
#pragma unroll
        for (int c = 0; c < 9; ++c) pm += phb[c * TT];
        pm *= (1.0f / 9.0f);
        float sp, cp;
        sincosf(pm, &sp, &cp);
        out[OFF_PH + p] = pm;
        u[9] = cp;
        u[10] = sp;
        u[11] = 0.0f;

        uint32_t* row32 = (uint32_t*)(smem + SM_A + (uint32_t)tid * KP_B);
#pragma unroll
        for (int q = 0; q < 6; ++q) {
            uint32_t hp, lp;
            split_pack(u[2 * q], u[2 * q + 1], hp, lp);
            row32[q] = hp;            // seg0: u_hi
            row32[8 + q] = lp;        // seg1: u_lo
            row32[16 + q] = hp;       // seg2: u_hi
        }
        row32[6] = 0u; row32[7] = 0u;
        row32[14] = 0u; row32[15] = 0u;
        row32[22] = 0u; row32[23] = 0u;
    }
    CP_WAIT(0);
    __syncthreads();   // A + B + cn all visible; no more barriers until epilogue

    // ---- GEMM + argmin. Warp w: rows 16w..16w+15, all 512 codes.
    const int m0 = wid * 16;

    const int mgrp = lane >> 3;     // 0..3
    const int mrow = lane & 7;
    const uint32_t a_base = sbase + SM_A
        + (uint32_t)(m0 + mrow + 8 * (mgrp & 1)) * KP_B
        + (uint32_t)(8 * (mgrp >> 1)) * 2u;
    const uint32_t b_row_off = (uint32_t)(8 * (mgrp >> 1) + mrow) * KP_B
        + (uint32_t)(8 * (mgrp & 1)) * 2u;

    // ---- A fragments register-resident: [kstep][4] = 12 regs
    uint32_t afr[3][4];
#pragma unroll
    for (int k = 0; k < 3; ++k)
        LDSM_X4(afr[k][0], afr[k][1], afr[k][2], afr[k][3],
                a_base + (uint32_t)k * 32u);

    float best[2];
    int bidx[2];
    best[0] = CUDART_INF_F; best[1] = CUDART_INF_F;
    bidx[0] = 0; bidx[1] = 0;

#pragma unroll 1
    for (int ch = 0; ch < 16; ++ch) {
        const uint32_t sBc = sbase + SM_B + (uint32_t)ch * (32 * KP_B);

        float acc[4][4];
#pragma unroll
        for (int j = 0; j < 4; ++j)
#pragma unroll
            for (int q = 0; q < 4; ++q) acc[j][q] = 0.0f;

#pragma unroll
        for (int g = 0; g < 2; ++g) {
            const uint32_t bb = sBc + (uint32_t)(g * 16) * KP_B + b_row_off;
            uint32_t bq[3][4];
#pragma unroll
            for (int k = 0; k < 3; ++k)
                LDSM_X4(bq[k][0], bq[k][1], bq[k][2], bq[k][3],
                        bb + (uint32_t)k * 32u);
#pragma unroll
            for (int k = 0; k < 3; ++k) {
                MMA16816(acc[2 * g],     afr[k], bq[k][0], bq[k][1]);
                MMA16816(acc[2 * g + 1], afr[k], bq[k][2], bq[k][3]);
            }
        }

        // running argmin (codes strictly increasing -> first-min kept)
#pragma unroll
        for (int j = 0; j < 4; ++j) {
            const int c0 = ch * 32 + (j >> 1) * 16 + (j & 1) * 8 + (lane & 3) * 2;
            const float n0v = scn[c0], n1v = scn[c0 + 1];
            const float d0 = fmaf(-2.0f, acc[j][0], n0v);
            const float d1 = fmaf(-2.0f, acc[j][1], n1v);
            const float d2 = fmaf(-2.0f, acc[j][2], n0v);
            const float d3 = fmaf(-2.0f, acc[j][3], n1v);
            if (d0 < best[0]) { best[0] = d0; bidx[0] = c0; }
            if (d1 < best[0]) { best[0] = d1; bidx[0] = c0 + 1; }
            if (d2 < best[1]) { best[1] = d2; bidx[1] = c0; }
            if (d3 < best[1]) { best[1] = d3; bidx[1] = c0 + 1; }
        }
    }

    // reduce across the 4 lanes sharing each row (quad)
#pragma unroll
    for (int off = 1; off <= 2; off <<= 1) {
#pragma unroll
        for (int s = 0; s < 2; ++s) {
            float ob = __shfl_xor_sync(0xffffffffu, best[s], off);
            int oi = __shfl_xor_sync(0xffffffffu, bidx[s], off);
            if (ob < best[s] || (ob == best[s] && oi < bidx[s])) {
                best[s] = ob; bidx[s] = oi;
            }
        }
    }
    if ((lane & 3) == 0) {
        const int r = lane >> 2;
        const int row_lo = m0 + r;
        const int row_hi = m0 + 8 + r;
        sidx[row_lo] = bidx[0];
        sidx[row_hi] = bidx[1];
        out[OFF_IDX + pbase + row_lo] = (float)bidx[0];
        out[OFF_IDX + pbase + row_hi] = (float)bidx[1];
    }
    __syncthreads();

    // quantized rows from fp32 codebook (L2-hot)
    const float4* cb4 = (const float4*)cb;
    for (int q = tid; q < MBLK * (CD / 4); q += 512) {
        const int pos = q >> 4;
        const int w = q & 15;
        ((float4*)(out + (size_t)(pbase + pos) * CD))[w] =
            cb4[(size_t)sidx[pos] * (CD / 4) + w];
    }
}

// ---------------- launch ----------------
extern "C" void kernel_launch(void* const* d_in, const int* in_sizes, int n_in,
                              void* d_out, int out_size) {
    const float* imu = (const float*)d_in[0];
    const float* Wm  = (const float*)d_in[1];
    const float* bm  = (const float*)d_in[2];
    const float* Wp  = (const float*)d_in[3];
    const float* bp  = (const float*)d_in[4];
    const float* cb  = (const float*)d_in[5];
    float* out = (float*)d_out;

    cudaFuncSetAttribute(fft_conv_kernel,
                         cudaFuncAttributeMaxDynamicSharedMemorySize, FFT_SMEM);
    fft_conv_kernel<<<NPAIR + NC / 16, 512, FFT_SMEM>>>(imu, cb, Wm, bm, Wp, bp);

    cudaFuncSetAttribute(quant_kernel,
                         cudaFuncAttributeMaxDynamicSharedMemorySize, SMEMSZ);
    quant_kernel<<<(BB * TT) / MBLK, 512, SMEMSZ>>>(imu, cb, out);
}